// round 17
// baseline (speedup 1.0000x reference)
#include <cuda_runtime.h>
#include <cuda_fp16.h>
#include <cstdint>

#define L_SEQ 2048
#define EMB   512
#define NHEAD 8
#define HDIM  64
#define NTYPE 10
#define KW    1024      // qkv weight width: [w_hi | w_lo]
#define QW    1024      // projected q width: [hi | lo]
#define QSCALE 0.18033688011112042f   // 0.125 * log2(e)

// ---------------------------------------------------------------------------
__device__ float g_ts[NHEAD * L_SEQ * 16];
__device__ uint8_t g_eid8[L_SEQ * L_SEQ];

__device__ __half g_aq[L_SEQ * EMB];      // hi-only activations
__device__ __half g_ak[L_SEQ * EMB];
__device__ __half g_av[L_SEQ * EMB];
__device__ __half g_wqkv[3 * EMB * KW];   // [w_hi | w_lo]
__device__ __half g_wo[EMB * EMB];        // hi-only, natural
__device__ __half g_sq[L_SEQ * QW];       // projected q (log2-scaled) [hi|lo]
__device__ __half g_sk[L_SEQ * EMB];      // projected k, fp16, natural
__device__ __half g_v16[L_SEQ * EMB];     // projected v, fp16, natural
__device__ __half g_actx[L_SEQ * EMB];    // ctx, fp16, natural
__device__ __half g_svt[NHEAD * HDIM * L_SEQ];  // [h][d][j] natural

// ---------------------------------------------------------------------------
__device__ __forceinline__ uint32_t packh(float lo, float hi) {
    uint32_t r;
    asm("cvt.rn.f16x2.f32 %0, %1, %2;" : "=r"(r) : "f"(hi), "f"(lo));
    return r;
}
__device__ __forceinline__ uint32_t ex2h2(float lo, float hi) {
    uint32_t r;
    asm("cvt.rn.f16x2.f32 %0, %1, %2;" : "=r"(r) : "f"(hi), "f"(lo));
    asm("ex2.approx.f16x2 %0, %0;" : "+r"(r));
    return r;
}
__device__ __forceinline__ float ex2f(float x) {
    float r;
    asm("ex2.approx.f32 %0, %1;" : "=f"(r) : "f"(x));
    return r;
}
__device__ __forceinline__ float2 unph(uint32_t u) {
    __half2 h = *reinterpret_cast<__half2*>(&u);
    return __half22float2(h);
}
__device__ __forceinline__ uint32_t smem_to_u32(const void* p) {
    uint32_t a;
    asm("{ .reg .u64 t; cvta.to.shared.u64 t, %1; cvt.u32.u64 %0, t; }"
        : "=r"(a) : "l"(p));
    return a;
}
__device__ __forceinline__ void mma16816(float* d, const uint32_t* a,
                                         uint32_t b0, uint32_t b1) {
    asm volatile(
        "mma.sync.aligned.m16n8k16.row.col.f32.f16.f16.f32 "
        "{%0,%1,%2,%3}, {%4,%5,%6,%7}, {%8,%9}, {%0,%1,%2,%3};"
        : "+f"(d[0]), "+f"(d[1]), "+f"(d[2]), "+f"(d[3])
        : "r"(a[0]), "r"(a[1]), "r"(a[2]), "r"(a[3]), "r"(b0), "r"(b1));
}
__device__ __forceinline__ void mma16816h(uint32_t* c, const uint32_t* a,
                                          uint32_t b0, uint32_t b1) {
    asm volatile(
        "mma.sync.aligned.m16n8k16.row.col.f16.f16.f16.f16 "
        "{%0,%1}, {%2,%3,%4,%5}, {%6,%7}, {%0,%1};"
        : "+r"(c[0]), "+r"(c[1])
        : "r"(a[0]), "r"(a[1]), "r"(a[2]), "r"(a[3]), "r"(b0), "r"(b1));
}
__device__ __forceinline__ void ldsm4(uint32_t& r0, uint32_t& r1,
                                      uint32_t& r2, uint32_t& r3, uint32_t a) {
    asm volatile("ldmatrix.sync.aligned.m8n8.x4.shared.b16 {%0,%1,%2,%3}, [%4];"
                 : "=r"(r0), "=r"(r1), "=r"(r2), "=r"(r3) : "r"(a));
}
__device__ __forceinline__ void cp16(uint32_t s, const void* g) {
    asm volatile("cp.async.cg.shared.global [%0], [%1], 16;"
                 :: "r"(s), "l"(g) : "memory");
}
#define CP_COMMIT asm volatile("cp.async.commit_group;" ::: "memory")

// ---------------------------------------------------------------------------
// ONE fused split kernel
// ---------------------------------------------------------------------------
__global__ __launch_bounds__(256) void split_all(
    const float* __restrict__ q, const float* __restrict__ k,
    const float* __restrict__ v, const float* __restrict__ w,
    const float* __restrict__ wo, const int* __restrict__ eid) {
    int idx = blockIdx.x * 256 + threadIdx.x;   // 0 .. 5242879
    if (idx < 3145728) {                        // activations: plain fp16
        const float* src = idx < 1048576 ? q : (idx < 2097152 ? k : v);
        __half* dst = idx < 1048576 ? g_aq : (idx < 2097152 ? g_ak : g_av);
        int li = idx & 1048575;
        dst[li] = __float2half(src[li]);
    } else if (idx < 3932160) {                 // w_in: [hi | lo]
        int li = idx - 3145728;
        int r = li >> 9, c = li & 511;
        float x = w[li];
        __half h = __float2half(x);
        __half l = __float2half(x - __half2float(h));
        __half* yr = g_wqkv + (size_t)r * KW;
        yr[c] = h; yr[512 + c] = l;
    } else if (idx < 4194304) {                 // w_out: hi only, natural
        int li = idx - 3932160;
        g_wo[li] = __float2half(wo[li]);
    } else {                                    // edge int4->uchar4
        int li = idx - 4194304;
        int4 e = *(const int4*)(eid + (size_t)li * 4);
        uchar4 c = make_uchar4((unsigned char)e.x, (unsigned char)e.y,
                               (unsigned char)e.z, (unsigned char)e.w);
        *(uchar4*)(g_eid8 + (size_t)li * 4) = c;
    }
}

// ---------------------------------------------------------------------------
// GEMM: 64 x (32*NF) block tile, 8 warps, warp tile 32 x (8*NF).
// mode 0: fp32 out; mode 1: q [hi|lo] width 1024; mode 4: plain fp16 width 512
// ---------------------------------------------------------------------------
template <int NF, int KITERS, int KAMASK>
__device__ __forceinline__ void gemm_core(const __half* __restrict__ A,
                                          const __half* __restrict__ B,
                                          const float* __restrict__ bias,
                                          float* __restrict__ Cf,
                                          __half* __restrict__ Cs,
                                          int cn0, int m0, float scale, int mode,
                                          int lda, int ldb) {
    constexpr int BROWS = 32 * NF;
    __shared__ __half As[2][64 * 40];
    __shared__ __half Bs[2][BROWS * 40];
    int tid = threadIdx.x, wid = tid >> 5, lane = tid & 31;
    int gid = lane >> 2, qt = lane & 3;
    int wm = wid >> 2, wn = wid & 3;

    float acc[2][NF][4] = {};
    uint32_t acch[2][NF][2] = {};
    int lrA = tid >> 2, lcA = (tid & 3) * 8;
    const __half* Ap = A + (size_t)(m0 + lrA) * lda + lcA;
    int lrB = (NF == 4) ? (tid >> 1) : (tid >> 2);
    int lcB = (NF == 4) ? ((tid & 1) * 16) : ((tid & 3) * 8);
    const __half* Bp = B + (size_t)lrB * ldb + lcB;
    uint32_t sA[2] = {smem_to_u32(&As[0][lrA * 40 + lcA]),
                      smem_to_u32(&As[1][lrA * 40 + lcA])};
    uint32_t sB[2] = {smem_to_u32(&Bs[0][lrB * 40 + lcB]),
                      smem_to_u32(&Bs[1][lrB * 40 + lcB])};

    cp16(sA[0], Ap);
    cp16(sB[0], Bp);
    if (NF == 4) cp16(sB[0] + 16, Bp + 8);
    CP_COMMIT;

    for (int kt = 0; kt < KITERS; kt++) {
        int cur = kt & 1;
        if (kt + 1 < KITERS) {
            int nx = cur ^ 1;
            const __half* a = Ap + ((kt + 1) & KAMASK) * 32;
            const __half* b = Bp + (kt + 1) * 32;
            cp16(sA[nx], a);
            cp16(sB[nx], b);
            if (NF == 4) cp16(sB[nx] + 16, b + 8);
            CP_COMMIT;
            asm volatile("cp.async.wait_group 1;" ::: "memory");
        } else {
            asm volatile("cp.async.wait_group 0;" ::: "memory");
        }
        __syncthreads();
        bool hi_term = (kt < 16);
        #pragma unroll
        for (int kc = 0; kc < 2; kc++) {
            uint32_t a[2][4];
            #pragma unroll
            for (int mf = 0; mf < 2; mf++) {
                int r = wm * 32 + mf * 16 + gid;
                int c = kc * 16 + qt * 2;
                a[mf][0] = *(const uint32_t*)&As[cur][r * 40 + c];
                a[mf][1] = *(const uint32_t*)&As[cur][(r + 8) * 40 + c];
                a[mf][2] = *(const uint32_t*)&As[cur][r * 40 + c + 8];
                a[mf][3] = *(const uint32_t*)&As[cur][(r + 8) * 40 + c + 8];
            }
            #pragma unroll
            for (int nf = 0; nf < NF; nf++) {
                int n = wn * (8 * NF) + nf * 8 + gid;
                int c = kc * 16 + qt * 2;
                uint32_t b0 = *(const uint32_t*)&Bs[cur][n * 40 + c];
                uint32_t b1 = *(const uint32_t*)&Bs[cur][n * 40 + c + 8];
                if (hi_term) {
                    #pragma unroll
                    for (int mf = 0; mf < 2; mf++)
                        mma16816(acc[mf][nf], a[mf], b0, b1);
                } else {
                    #pragma unroll
                    for (int mf = 0; mf < 2; mf++)
                        mma16816h(acch[mf][nf], a[mf], b0, b1);
                }
            }
        }
        __syncthreads();
    }
    #pragma unroll
    for (int mf = 0; mf < 2; mf++) {
        int r = m0 + wm * 32 + mf * 16 + gid;
        #pragma unroll
        for (int nf = 0; nf < NF; nf++) {
            int cb = wn * (8 * NF) + nf * 8 + qt * 2;
            float b0 = __ldg(bias + cb), b1 = __ldg(bias + cb + 1);
            float2 c0 = unph(acch[mf][nf][0]);
            float2 c1 = unph(acch[mf][nf][1]);
            float v00 = scale * (acc[mf][nf][0] + c0.x + b0);
            float v01 = scale * (acc[mf][nf][1] + c0.y + b1);
            float v10 = scale * (acc[mf][nf][2] + c1.x + b0);
            float v11 = scale * (acc[mf][nf][3] + c1.y + b1);
            int col = cn0 + cb;
            if (mode == 0) {
                *(float2*)&Cf[(size_t)r * EMB + col]       = make_float2(v00, v01);
                *(float2*)&Cf[(size_t)(r + 8) * EMB + col] = make_float2(v10, v11);
            } else if (mode == 1) {      // q: [hi|lo], width 1024
                float h00 = __half2float(__float2half(v00));
                float h01 = __half2float(__float2half(v01));
                float h10 = __half2float(__float2half(v10));
                float h11 = __half2float(__float2half(v11));
                __half* d0 = Cs + (size_t)r * QW + col;
                __half* d1 = Cs + (size_t)(r + 8) * QW + col;
                *(uint32_t*)d0         = packh(h00, h01);
                *(uint32_t*)(d0 + 512) = packh(v00 - h00, v01 - h01);
                *(uint32_t*)d1         = packh(h10, h11);
                *(uint32_t*)(d1 + 512) = packh(v10 - h10, v11 - h11);
            } else {                     // plain fp16, width 512
                *(uint32_t*)(Cs + (size_t)r * EMB + col)       = packh(v00, v01);
                *(uint32_t*)(Cs + (size_t)(r + 8) * EMB + col) = packh(v10, v11);
            }
        }
    }
}

__global__ void __launch_bounds__(256, 2) gemm_qkv_kernel(const float* __restrict__ bias) {
    int m0 = blockIdx.x * 64;
    int nt = blockIdx.y;          // 0..11
    int sect = nt >> 2;
    int cn0 = (nt & 3) * 128;
    const __half* Bw = g_wqkv + (size_t)nt * 128 * KW;
    if (sect == 0)
        gemm_core<4, 32, 15>(g_aq, Bw, bias + nt * 128, nullptr, g_sq,
                             cn0, m0, QSCALE, 1, EMB, KW);
    else if (sect == 1)
        gemm_core<4, 16, 15>(g_ak, Bw, bias + nt * 128, nullptr, g_sk,
                             cn0, m0, 1.0f, 4, EMB, KW);
    else                  // v: fp16 direct
        gemm_core<4, 16, 15>(g_av, Bw, bias + nt * 128, nullptr, g_v16,
                             cn0, m0, 1.0f, 4, EMB, KW);
}
__global__ void __launch_bounds__(256, 2) gemm_out_kernel(const float* __restrict__ bias,
                                                          float* __restrict__ C) {
    gemm_core<2, 16, 1023>(g_actx, g_wo + (size_t)blockIdx.y * 64 * EMB,
                           bias + blockIdx.y * 64, C, nullptr, blockIdx.y * 64,
                           blockIdx.x * 64, 1.0f, 0, EMB, EMB);
}

// ---------------------------------------------------------------------------
// Fused: V transpose fp16->fp16 (blocks 0..255) + type_scores (256..2303)
// ---------------------------------------------------------------------------
__global__ __launch_bounds__(256) void tsvt_kernel(const float* __restrict__ edge_embs) {
    __shared__ __half tileh[64 * 72];
    __shared__ float emb[NTYPE * HDIM];
    int tid = threadIdx.x;
    if (blockIdx.x < 256) {
        int h = blockIdx.x >> 5, j0 = (blockIdx.x & 31) * 64;
        {   // load 64 j-rows x 64 halfs
            int row = tid >> 2, cg = (tid & 3) * 16;
            const __half* src = g_v16 + (size_t)(j0 + row) * EMB + h * HDIM + cg;
            *(uint4*)&tileh[row * 72 + cg]     = *(const uint4*)src;
            *(uint4*)&tileh[row * 72 + cg + 8] = *(const uint4*)(src + 8);
        }
        __syncthreads();
        int d = tid >> 2, jg = (tid & 3) * 16;
        uint32_t hw[8];
        #pragma unroll
        for (int p = 0; p < 8; p++) {
            uint32_t lo = __half_as_ushort(tileh[(jg + 2 * p) * 72 + d]);
            uint32_t hi = __half_as_ushort(tileh[(jg + 2 * p + 1) * 72 + d]);
            hw[p] = lo | (hi << 16);
        }
        __half* dsth = g_svt + ((size_t)(h * 64 + d) * L_SEQ + j0 + jg);
        *(uint4*)dsth       = make_uint4(hw[0], hw[1], hw[2], hw[3]);
        *(uint4*)(dsth + 8) = make_uint4(hw[4], hw[5], hw[6], hw[7]);
    } else {
        for (int i = tid; i < NTYPE * HDIM; i += 256) emb[i] = edge_embs[i];
        __syncthreads();
        int warp = (blockIdx.x - 256) * 8 + (tid >> 5);
        int lane = tid & 31;
        int h = warp >> 11, i = warp & (L_SEQ - 1);
        const __half* qr = g_sq + (size_t)i * QW + h * HDIM + lane * 2;
        float2 qh = __half22float2(*(const __half2*)qr);
        float2 ql = __half22float2(*(const __half2*)(qr + 512));
        float2 qv = make_float2(qh.x + ql.x, qh.y + ql.y);
        float s[NTYPE];
        #pragma unroll
        for (int t = 0; t < NTYPE; t++) {
            float2 e = *(const float2*)(emb + t * HDIM + lane * 2);
            s[t] = qv.x * e.x + qv.y * e.y;
        }
        #pragma unroll
        for (int off = 16; off > 0; off >>= 1)
            #pragma unroll
            for (int t = 0; t < NTYPE; t++)
                s[t] += __shfl_xor_sync(0xffffffffu, s[t], off);
        if (lane == 0) {
            float* dst = g_ts + (size_t)warp * 16;
            #pragma unroll
            for (int t = 0; t < NTYPE; t++) dst[t] = s[t];
        }
    }
}

// ---------------------------------------------------------------------------
// Flash attention: i-tile 64, 2 independent 4-warp groups, 2 CTAs/SM.
// PAIRED-tile loading: each cp.async phase fetches the group's 32-j slices of
// TWO consecutive 64-j tiles; one barrier pair covers both sub-tiles.
// ldmatrix fragments; pitches Q/K 144B, V 80B (16B-aligned, conflict-free).
// smem: Q 9216 @0; K 2grp x 2pair x 9216 @9216; V 2grp x 2pair x 10240 @46080;
// Ts 4096 @87040. total 91136. 2 CTAs/SM.
// ---------------------------------------------------------------------------
#define SM_K 9216
#define SM_V 46080
#define SM_T 87040
#define ATTN_SMEM 91136

__global__ void __launch_bounds__(256, 2) attn_mma_kernel() {
    extern __shared__ char smb[];
    float* Ts = (float*)(smb + SM_T);
    uint32_t sbase = smem_to_u32(smb);

    int h = blockIdx.y;
    int i0 = blockIdx.x * 64;
    int tid = threadIdx.x, wid = tid >> 5, lane = tid & 31;
    int gid = lane >> 2, qt = lane & 3;
    int ngrp = wid >> 2, wg = wid & 3, gtid = tid & 127;
    const uint32_t ones2 = 0x3C003C00u;
    const uint32_t kgrp = sbase + SM_K + ngrp * 18432;
    const uint32_t vgrp = sbase + SM_V + ngrp * 20480;

    // load this group's 32-j slices of tiles (jp) and (jp+64): 8 cp16/thread
    auto load_kv = [&](int jp, int buf) {
        {   // K: 2 x (32 rows x 128B), pitch 144B
            int row = gtid >> 2, part = gtid & 3;
            const __half* s0 = g_sk + (size_t)(jp + ngrp * 32 + row) * EMB
                               + h * HDIM + part * 16;
            uint32_t d0 = kgrp + buf * 9216 + row * 144 + part * 32;
            cp16(d0, s0); cp16(d0 + 16, s0 + 8);
            const __half* s1 = s0 + (size_t)64 * EMB;
            uint32_t d1 = d0 + 4608;
            cp16(d1, s1); cp16(d1 + 16, s1 + 8);
        }
        {   // V: 2 x (64 d-rows x 64B), pitch 80B
            int row = gtid >> 1, part = gtid & 1;
            const __half* s0 = g_svt + (size_t)(h * 64 + row) * L_SEQ
                               + jp + ngrp * 32 + part * 16;
            uint32_t d0 = vgrp + buf * 10240 + row * 80 + part * 32;
            cp16(d0, s0); cp16(d0 + 16, s0 + 8);
            const __half* s1 = s0 + 64;
            uint32_t d1 = d0 + 5120;
            cp16(d1, s1); cp16(d1 + 16, s1 + 8);
        }
    };

    {   // Q tile (64 rows x 128B, pitch 144B) + Ts
        int row = tid >> 2, part = tid & 3;
        const __half* src = g_sq + (size_t)(i0 + row) * QW + h * HDIM + part * 16;
        uint32_t dst = sbase + row * 144 + part * 32;
        cp16(dst, src); cp16(dst + 16, src + 8);
        *(float4*)(Ts + row * 16 + part * 4) =
            *(const float4*)(g_ts + ((size_t)h * L_SEQ + i0 + row) * 16 + part * 4);
    }
    load_kv(0, 0);
    CP_COMMIT;
    asm volatile("cp.async.wait_group 0;" ::: "memory");
    __syncthreads();

    int r0 = wg * 16 + gid;
    int lm_row = (lane & 7) | (((lane >> 3) & 1) << 3);
    int lm_hi  = (lane >> 4) & 1;

    uint32_t qh[4][4];
    {
        uint32_t qa = sbase + (wg * 16 + lm_row) * 144 + lm_hi * 16;
        #pragma unroll
        for (int kc = 0; kc < 4; kc++)
            ldsm4(qh[kc][0], qh[kc][1], qh[kc][2], qh[kc][3], qa + kc * 32);
    }

    float o[8][4] = {};
    float rm0 = -1e30f, rm1 = -1e30f, rl0 = 0.f, rl1 = 0.f;
    const float* T0 = Ts + r0 * 16;
    const float* T1 = T0 + 128;
    const uint8_t* eb0 = g_eid8 + (size_t)(i0 + r0) * L_SEQ;
    const uint8_t* eb1 = eb0 + 8 * L_SEQ;
    const int bid = ngrp + 1;
    const uint32_t klm = kgrp + lm_row * 144 + lm_hi * 16;
    const uint32_t vlm = vgrp + lm_row * 80 + lm_hi * 16;

    for (int tp = 0; tp < 16; tp++) {
        int cur = tp & 1;
        if (tp + 1 < 16) {
            load_kv((tp + 1) * 128, cur ^ 1);
            CP_COMMIT;
            asm volatile("cp.async.wait_group 1;" ::: "memory");
        } else {
            asm volatile("cp.async.wait_group 0;" ::: "memory");
        }
        asm volatile("bar.sync %0, 128;" :: "r"(bid) : "memory");

        #pragma unroll
        for (int sub = 0; sub < 2; sub++) {
            int j0 = tp * 128 + sub * 64;
            uint32_t ka = klm + cur * 9216 + sub * 4608;
            uint32_t va = vlm + cur * 10240 + sub * 5120;

            // ---- edge-id prefetch (int8) ----
            unsigned short e0r[4], e1r[4];
            #pragma unroll
            for (int ntl = 0; ntl < 4; ntl++) {
                int col = j0 + ngrp * 32 + ntl * 8 + qt * 2;
                e0r[ntl] = *(const unsigned short*)(eb0 + col);
                e1r[ntl] = *(const unsigned short*)(eb1 + col);
            }

            // ---- S = qh*kh via ldmatrix B-fragments ----
            float sa[4][4] = {};
            #pragma unroll
            for (int kc = 0; kc < 4; kc++) {
                uint32_t b0, b1, b2, b3, c0, c1, c2, c3;
                ldsm4(b0, b1, b2, b3, ka + kc * 32);
                ldsm4(c0, c1, c2, c3, ka + 16 * 144 + kc * 32);
                mma16816(sa[0], qh[kc], b0, b2);
                mma16816(sa[1], qh[kc], b1, b3);
                mma16816(sa[2], qh[kc], c0, c2);
                mma16816(sa[3], qh[kc], c1, c3);
            }
            #pragma unroll
            for (int ntl = 0; ntl < 4; ntl++) {
                sa[ntl][0] += T0[e0r[ntl] & 0xFF];
                sa[ntl][1] += T0[e0r[ntl] >> 8];
                sa[ntl][2] += T1[e1r[ntl] & 0xFF];
                sa[ntl][3] += T1[e1r[ntl] >> 8];
            }

            // ---- online softmax (base 2) ----
            float mx0 = -1e30f, mx1 = -1e30f;
            #pragma unroll
            for (int ntl = 0; ntl < 4; ntl++) {
                mx0 = fmaxf(mx0, fmaxf(sa[ntl][0], sa[ntl][1]));
                mx1 = fmaxf(mx1, fmaxf(sa[ntl][2], sa[ntl][3]));
            }
            mx0 = fmaxf(mx0, __shfl_xor_sync(0xffffffffu, mx0, 1));
            mx0 = fmaxf(mx0, __shfl_xor_sync(0xffffffffu, mx0, 2));
            mx1 = fmaxf(mx1, __shfl_xor_sync(0xffffffffu, mx1, 1));
            mx1 = fmaxf(mx1, __shfl_xor_sync(0xffffffffu, mx1, 2));
            float mn0 = fmaxf(rm0, mx0), mn1 = fmaxf(rm1, mx1);
            bool skip = __all_sync(0xffffffffu, (mn0 == rm0) & (mn1 == rm1));

            uint32_t ph[2][4];
            float ls[4] = {};
            #pragma unroll
            for (int kcp = 0; kcp < 2; kcp++) {
                const float* t0v = sa[2 * kcp];
                const float* t1v = sa[2 * kcp + 1];
                ph[kcp][0] = ex2h2(t0v[0] - mn0, t0v[1] - mn0);
                ph[kcp][1] = ex2h2(t0v[2] - mn1, t0v[3] - mn1);
                ph[kcp][2] = ex2h2(t1v[0] - mn0, t1v[1] - mn0);
                ph[kcp][3] = ex2h2(t1v[2] - mn1, t1v[3] - mn1);
                mma16816(ls, ph[kcp], ones2, ones2);
            }
            if (!skip) {
                float c0 = ex2f(rm0 - mn0), c1 = ex2f(rm1 - mn1);
                rl0 *= c0; rl1 *= c1;
                #pragma unroll
                for (int dt = 0; dt < 8; dt++) {
                    o[dt][0] *= c0; o[dt][1] *= c0;
                    o[dt][2] *= c1; o[dt][3] *= c1;
                }
                rm0 = mn0; rm1 = mn1;
            }
            rl0 += ls[0];
            rl1 += ls[2];

            // ---- PV via ldmatrix V B-fragments ----
            #pragma unroll
            for (int kcp = 0; kcp < 2; kcp++) {
                #pragma unroll
                for (int b = 0; b < 4; b++) {
                    uint32_t v0, v1, v2, v3;
                    ldsm4(v0, v1, v2, v3, va + b * 16 * 80 + kcp * 32);
                    mma16816(o[2 * b],     ph[kcp], v0, v2);
                    mma16816(o[2 * b + 1], ph[kcp], v1, v3);
                }
            }
        }
        asm volatile("bar.sync %0, 128;" :: "r"(bid) : "memory");
    }

    // ---- combine the two n-groups (reuse K region: 36864 >= 17408) ----
    __syncthreads();
    float* co = (float*)(smb + SM_K);            // [64][66]
    float* cm = (float*)(smb + SM_K + 16896);
    float* cl = (float*)(smb + SM_K + 17152);
    if (ngrp == 1) {
        if (qt == 0) {
            cm[r0] = rm0; cm[r0 + 8] = rm1;
            cl[r0] = rl0; cl[r0 + 8] = rl1;
        }
        #pragma unroll
        for (int dt = 0; dt < 8; dt++) {
            int c = dt * 8 + qt * 2;
            *(float2*)&co[r0 * 66 + c]       = make_float2(o[dt][0], o[dt][1]);
            *(float2*)&co[(r0 + 8) * 66 + c] = make_float2(o[dt][2], o[dt][3]);
        }
    }
    __syncthreads();
    if (ngrp == 0) {
        float m1a = cm[r0], l1a = cl[r0];
        float m1b = cm[r0 + 8], l1b = cl[r0 + 8];
        float M0 = fmaxf(rm0, m1a), M1 = fmaxf(rm1, m1b);
        float a0 = ex2f(rm0 - M0), b0 = ex2f(m1a - M0);
        float a1 = ex2f(rm1 - M1), b1 = ex2f(m1b - M1);
        float inv0 = 1.0f / (rl0 * a0 + l1a * b0);
        float inv1 = 1.0f / (rl1 * a1 + l1b * b1);
        __half* dst0 = g_actx + (size_t)(i0 + r0) * EMB + h * HDIM;
        __half* dst1 = g_actx + (size_t)(i0 + r0 + 8) * EMB + h * HDIM;
        #pragma unroll
        for (int dt = 0; dt < 8; dt++) {
            int c = dt * 8 + qt * 2;
            float v0 = (o[dt][0] * a0 + co[r0 * 66 + c] * b0) * inv0;
            float v1 = (o[dt][1] * a0 + co[r0 * 66 + c + 1] * b0) * inv0;
            float w0 = (o[dt][2] * a1 + co[(r0 + 8) * 66 + c] * b1) * inv1;
            float w1 = (o[dt][3] * a1 + co[(r0 + 8) * 66 + c + 1] * b1) * inv1;
            *(uint32_t*)(dst0 + c) = packh(v0, v1);
            *(uint32_t*)(dst1 + c) = packh(w0, w1);
        }
    }
}

// ---------------------------------------------------------------------------
extern "C" void kernel_launch(void* const* d_in, const int* in_sizes, int n_in,
                              void* d_out, int out_size)
{
    const float* query = (const float*)d_in[0];
    const float* key   = (const float*)d_in[1];
    const float* value = (const float*)d_in[2];
    const int*   eid   = (const int*)d_in[3];
    const float* w_in  = (const float*)d_in[4];
    const float* b_in  = (const float*)d_in[5];
    const float* w_out = (const float*)d_in[6];
    const float* b_out = (const float*)d_in[7];
    const float* embK  = (const float*)d_in[8];
    float* out = (float*)d_out;

    // launch 0: splits + edge int8 compression
    split_all<<<20480, 256>>>(query, key, value, w_in, w_out, eid);

    // launch 1: QKV projection (q: hi+lo; k,v: fp16 direct)
    dim3 qkv_grid(L_SEQ / 64, 12);
    gemm_qkv_kernel<<<qkv_grid, 256>>>(b_in);

    // launch 2: V transpose (fp16) + type scores
    tsvt_kernel<<<2304, 256>>>(embK);

    // launch 3: flash attention (paired-tile loading)
    cudaFuncSetAttribute(attn_mma_kernel, cudaFuncAttributeMaxDynamicSharedMemorySize,
                         ATTN_SMEM);
    dim3 attn_grid(L_SEQ / 64, NHEAD);
    attn_mma_kernel<<<attn_grid, 256, ATTN_SMEM>>>();

    // launch 4: out projection
    dim3 out_grid(L_SEQ / 64, EMB / 64);
    gemm_out_kernel<<<out_grid, 256>>>(b_out, out);
}